// round 12
// baseline (speedup 1.0000x reference)
#include <cuda_runtime.h>

#define NN 1024
#define NMASK 1023
#define NH 512
#define TC 32          // subband cols per block
#define TR 32          // subband rows per block
#define HROWS 70       // halo rows: 2*32 + 6
#define TSTRIDE 72     // intermediate row stride in floats

// lo[j] = w[7-j] (index reversal, free); hi[j] = (j odd) ? w[j] : -w[j]
// (negation folded into the FFMA operand modifier, free in SASS).
#define FMA_LO(v, j, s) (s) = fmaf((v), w[7 - (j)], (s))
#define FMA_HI(v, j, s) (s) = ((j) & 1) ? fmaf((v), w[(j)], (s)) \
                                        : fmaf((v), -w[(j)], (s))

__global__ __launch_bounds__(256, 7)
void wav2d_kernel(const float* __restrict__ x,
                  const float* __restrict__ bmt,
                  float* __restrict__ out)
{
    __shared__ float tmp[HROWS * TSTRIDE];   // 20160 B

    const int tid = threadIdx.x;
    const int b  = blockIdx.z;
    const int r0 = blockIdx.y * TR;
    const int c0 = blockIdx.x * TC;

    float w[8];
    #pragma unroll
    for (int j = 0; j < 8; ++j) w[j] = __ldg(&bmt[j]);

    const float* xb = x + (size_t)b * NN * NN;
    const int gr0  = 2 * r0 - 3;   // first halo row (wrapped)
    const int gc0a = 2 * c0 - 4;   // first halo col, 16B-aligned when in-bounds

    // ---- Phase 1: horizontal filter, global -> regs -> smem ----
    // Task t (of 70*16=1120): row = t>>4, pair = t&15 -> output cols
    // 2*pair, 2*pair+1. Loads 3 float4 at 16B LANE STRIDE (fully coalesced:
    // 16 consecutive lanes cover 256B contiguous per row group), uses f[1..10].
    const bool xint = (blockIdx.x >= 1) & (blockIdx.x <= 14);
    #pragma unroll
    for (int it = 0; it < 5; ++it) {
        int task = tid + it * 256;
        if (task < HROWS * 16) {
            int row  = task >> 4;
            int pair = task & 15;
            int gr   = (gr0 + row) & NMASK;
            const float* rowp = xb + (size_t)gr * NN;

            float f[12];
            if (xint) {
                const float4* p = (const float4*)(rowp + gc0a) + pair;
                float4 v0 = __ldg(p), v1 = __ldg(p + 1), v2 = __ldg(p + 2);
                f[0]=v0.x; f[1]=v0.y; f[2]=v0.z;  f[3]=v0.w;
                f[4]=v1.x; f[5]=v1.y; f[6]=v1.z;  f[7]=v1.w;
                f[8]=v2.x; f[9]=v2.y; f[10]=v2.z; f[11]=v2.w;
            } else {
                int base = gc0a + 4 * pair;
                #pragma unroll
                for (int j = 0; j < 12; ++j)
                    f[j] = __ldg(&rowp[(base + j) & NMASK]);
            }

            float sA0 = 0.f, sD0 = 0.f, sA1 = 0.f, sD1 = 0.f;
            #pragma unroll
            for (int j = 0; j < 8; ++j) {
                FMA_LO(f[1 + j], j, sA0);  FMA_HI(f[1 + j], j, sD0);
                FMA_LO(f[3 + j], j, sA1);  FMA_HI(f[3 + j], j, sD1);
            }
            *(float2*)&tmp[row * TSTRIDE + 2 * pair]      = make_float2(sA0, sA1);
            *(float2*)&tmp[row * TSTRIDE + 32 + 2 * pair] = make_float2(sD0, sD1);
        }
    }
    __syncthreads();

    // ---- Phase 2: vertical filter, warp-uniform; 8 output rows/thread ----
    // warp g: arr = g&1 (A cols [0,32) or D cols [32,64)), q = g>>1 (0..3).
    // Output rows 8q..8q+7 need tmp rows 16q..16q+21 (sliding window of 22).
    {
        const int tx  = tid & 31;
        const int g   = tid >> 5;
        const int arr = g & 1;
        const int q   = g >> 1;

        float sL[8] = {0,0,0,0,0,0,0,0};
        float sH[8] = {0,0,0,0,0,0,0,0};

        const float* col = &tmp[(16 * q) * TSTRIDE + 32 * arr + tx];
        #pragma unroll
        for (int i = 0; i < 22; ++i) {
            float v = col[i * TSTRIDE];
            #pragma unroll
            for (int m = 0; m < 8; ++m) {
                int j = i - 2 * m;
                if (j >= 0 && j < 8) {
                    FMA_LO(v, j, sL[m]);
                    FMA_HI(v, j, sH[m]);
                }
            }
        }

        // arr=0 -> top half rows; arr=1 -> bottom half (+NH).
        // Vertical low-pass -> left cols; high-pass -> right cols (+NH).
        float* ob = out + (size_t)b * NN * NN + (size_t)(arr * NH) * NN;
        const int C = c0 + tx;
        #pragma unroll
        for (int m = 0; m < 8; ++m) {
            int R = r0 + 8 * q + m;
            ob[R * NN + C]      = sL[m];
            ob[R * NN + C + NH] = sH[m];
        }
    }
}

extern "C" void kernel_launch(void* const* d_in, const int* in_sizes, int n_in,
                              void* d_out, int out_size)
{
    const float* x   = (const float*)d_in[0];
    const float* bmt = (const float*)d_in[1];
    float* out = (float*)d_out;

    const int B = in_sizes[0] / (NN * NN);   // 32
    dim3 grid(NH / TC, NH / TR, B);          // (16,16,32) = 8192 CTAs
    wav2d_kernel<<<grid, 256>>>(x, bmt, out);
}